// round 2
// baseline (speedup 1.0000x reference)
#include <cuda_runtime.h>
#include <math.h>

#define BB 2
#define TT 2048
#define CC 1024
#define HH 16
#define DD 64
#define C3 (3*CC)

// Scratch (allocation-free rule: __device__ globals)
__device__ float g_qkv[(size_t)BB * TT * C3]; // [B*T, 3C]
__device__ float g_y[(size_t)BB * TT * CC];   // [B*T, C]

// ---------------------------------------------------------------------------
// Classic 128x128 SGEMM, 256 threads, 8x8 micro-tile, K-step 8.
// A [M,K] row-major, B [K,N] row-major, C [M,N] row-major.
// All dims assumed divisible (M%128==0, N%128==0, K%8==0) — true here.
// ---------------------------------------------------------------------------
__global__ __launch_bounds__(256) void sgemm128(
    const float* __restrict__ A, const float* __restrict__ B,
    float* __restrict__ C, int M, int N, int K)
{
    __shared__ float As[8][128];
    __shared__ float Bs[8][128];

    const int tid  = threadIdx.x;
    const int bm   = blockIdx.y * 128;
    const int bn   = blockIdx.x * 128;
    const int tx   = tid & 15;       // 0..15
    const int ty   = tid >> 4;       // 0..15
    const int arow = tid >> 1;       // 0..127
    const int acol = (tid & 1) * 4;  // 0 or 4
    const int brow = tid >> 5;       // 0..7
    const int bcol = (tid & 31) * 4; // 0..124

    float acc[8][8];
#pragma unroll
    for (int i = 0; i < 8; i++)
#pragma unroll
        for (int j = 0; j < 8; j++) acc[i][j] = 0.f;

    const float* Aptr = A + (size_t)(bm + arow) * K + acol;
    const float* Bptr = B + (size_t)brow * N + bn + bcol;

    for (int k0 = 0; k0 < K; k0 += 8) {
        float4 av = *(const float4*)(Aptr + k0);
        float4 bv = *(const float4*)(Bptr + (size_t)k0 * N);
        As[acol + 0][arow] = av.x;
        As[acol + 1][arow] = av.y;
        As[acol + 2][arow] = av.z;
        As[acol + 3][arow] = av.w;
        *(float4*)&Bs[brow][bcol] = bv;
        __syncthreads();

#pragma unroll
        for (int kk = 0; kk < 8; kk++) {
            float a[8], b[8];
            *(float4*)&a[0] = *(const float4*)&As[kk][ty * 8];
            *(float4*)&a[4] = *(const float4*)&As[kk][ty * 8 + 4];
            *(float4*)&b[0] = *(const float4*)&Bs[kk][tx * 8];
            *(float4*)&b[4] = *(const float4*)&Bs[kk][tx * 8 + 4];
#pragma unroll
            for (int i = 0; i < 8; i++)
#pragma unroll
                for (int j = 0; j < 8; j++)
                    acc[i][j] += a[i] * b[j];
        }
        __syncthreads();
    }

#pragma unroll
    for (int i = 0; i < 8; i++) {
        float* Cp = C + (size_t)(bm + ty * 8 + i) * N + bn + tx * 8;
        *(float4*)Cp       = make_float4(acc[i][0], acc[i][1], acc[i][2], acc[i][3]);
        *(float4*)(Cp + 4) = make_float4(acc[i][4], acc[i][5], acc[i][6], acc[i][7]);
    }
}

// ---------------------------------------------------------------------------
// Causal flash-attention, fp32. One query per thread, 128 queries per block.
// Key/value tiles of 32 staged through shared memory; online softmax.
// The reference's "window" term is dead code (col<=row implies col-row<16),
// so the mask is pure causal.
// qkv layout: [B*T, 3C]; q at col h*64, k at C + h*64, v at 2C + h*64.
// ---------------------------------------------------------------------------
#define TQ 128
#define TK 32

__global__ __launch_bounds__(128) void attn_kernel(
    const float* __restrict__ qkv, float* __restrict__ y)
{
    __shared__ float Ks[TK][DD];
    __shared__ float Vs[TK][DD];
    __shared__ float Sc[TQ][TK + 1];

    const int bh = blockIdx.x;                 // 0..31
    const int b  = bh >> 4;
    const int h  = bh & 15;
    const int rt = gridDim.y - 1 - blockIdx.y; // heavy (late) row-tiles first
    const int r0 = rt * TQ;
    const int tid = threadIdx.x;
    const int r   = r0 + tid;

    const float* base = qkv + (size_t)b * TT * C3;
    const float scale = 0.125f; // 1/sqrt(64)

    // Load this thread's query row into registers (pre-scaled).
    float q[DD];
    {
        const float* qp = base + (size_t)r * C3 + h * DD;
#pragma unroll
        for (int d = 0; d < DD; d += 4) {
            float4 v = *(const float4*)(qp + d);
            q[d] = v.x * scale; q[d+1] = v.y * scale;
            q[d+2] = v.z * scale; q[d+3] = v.w * scale;
        }
    }

    float acc[DD];
#pragma unroll
    for (int d = 0; d < DD; d++) acc[d] = 0.f;
    float m = -1e30f, l = 0.f;

    const float* kbase = base + CC + h * DD;
    const float* vbase = base + 2 * CC + h * DD;

    const int kend = r0 + TQ; // last tile start is < kend
    for (int k0 = 0; k0 < kend; k0 += TK) {
        // Cooperative coalesced load of K/V tiles: TK*DD = 2048 floats each.
        // 512 float4 per tile; 128 threads -> 4 float4 each.
#pragma unroll
        for (int i = 0; i < 4; i++) {
            int f   = i * 128 + tid;      // 0..511
            int row = f >> 4;             // 0..31
            int col = (f & 15) * 4;       // 0..60
            size_t goff = (size_t)(k0 + row) * C3 + col;
            *(float4*)&Ks[row][col] = *(const float4*)(kbase + goff);
            *(float4*)&Vs[row][col] = *(const float4*)(vbase + goff);
        }
        __syncthreads();

        // Scores for this tile (masked causal), running tile max.
        float tmax = -1e30f;
#pragma unroll 4
        for (int s = 0; s < TK; s++) {
            float sum = 0.f;
#pragma unroll
            for (int d = 0; d < DD; d += 4) {
                float4 kv = *(const float4*)&Ks[s][d];
                sum += q[d] * kv.x + q[d+1] * kv.y
                     + q[d+2] * kv.z + q[d+3] * kv.w;
            }
            sum = ((k0 + s) <= r) ? sum : -1e30f;
            Sc[tid][s] = sum;
            tmax = fmaxf(tmax, sum);
        }

        // Online softmax rescale (once per tile).
        float mnew = fmaxf(m, tmax);
        float corr = __expf(m - mnew);
        l *= corr;
#pragma unroll
        for (int d = 0; d < DD; d++) acc[d] *= corr;

#pragma unroll 4
        for (int s = 0; s < TK; s++) {
            float p = __expf(Sc[tid][s] - mnew);
            l += p;
#pragma unroll
            for (int d = 0; d < DD; d += 4) {
                float4 vv = *(const float4*)&Vs[s][d];
                acc[d]   += p * vv.x; acc[d+1] += p * vv.y;
                acc[d+2] += p * vv.z; acc[d+3] += p * vv.w;
            }
        }
        m = mnew;
        __syncthreads();
    }

    float inv = 1.f / l;
    float* yp = y + ((size_t)b * TT + r) * CC + h * DD;
#pragma unroll
    for (int d = 0; d < DD; d += 4) {
        *(float4*)(yp + d) = make_float4(acc[d] * inv, acc[d+1] * inv,
                                         acc[d+2] * inv, acc[d+3] * inv);
    }
}

// ---------------------------------------------------------------------------
extern "C" void kernel_launch(void* const* d_in, const int* in_sizes, int n_in,
                              void* d_out, int out_size)
{
    const float* x      = (const float*)d_in[0]; // [B*T, C]
    const float* w_qkv  = (const float*)d_in[1]; // [C, 3C]
    const float* w_proj = (const float*)d_in[2]; // [C, C]
    float* out = (float*)d_out;                  // [B*T, C]

    void *pqkv, *py;
    cudaGetSymbolAddress(&pqkv, g_qkv);
    cudaGetSymbolAddress(&py, g_y);
    float* qkv = (float*)pqkv;
    float* yattn = (float*)py;

    const int M = BB * TT; // 4096

    // 1) QKV projection: [4096,1024] @ [1024,3072]
    dim3 g1(C3 / 128, M / 128);
    sgemm128<<<g1, 256>>>(x, w_qkv, qkv, M, C3, CC);

    // 2) Causal attention
    dim3 g2(BB * HH, TT / TQ);
    attn_kernel<<<g2, 128>>>(qkv, yattn);

    // 3) Output projection: [4096,1024] @ [1024,1024]
    dim3 g3(CC / 128, M / 128);
    sgemm128<<<g3, 256>>>(yattn, w_proj, out, M, CC, CC);
}

// round 6
// speedup vs baseline: 1.5299x; 1.5299x over previous
#include <cuda_runtime.h>
#include <cuda_bf16.h>
#include <math.h>
#include <stdint.h>

#define BB 2
#define TT 2048
#define CC 1024
#define HH 16
#define DD 64
#define C3 (3*CC)
#define MM (BB*TT)   // 4096

// ---------------- scratch (__device__ globals; allocation-free rule) -------
__device__ float         g_qkv[(size_t)MM * C3];       // [4096, 3072] fp32
__device__ __nv_bfloat16 g_xh[(size_t)MM * CC];
__device__ __nv_bfloat16 g_xl[(size_t)MM * CC];
__device__ __nv_bfloat16 g_wqkvT_h[(size_t)C3 * CC];   // w_qkv^T [3072,1024]
__device__ __nv_bfloat16 g_wqkvT_l[(size_t)C3 * CC];
__device__ __nv_bfloat16 g_wprojT_h[(size_t)CC * CC];  // w_proj^T [1024,1024]
__device__ __nv_bfloat16 g_wprojT_l[(size_t)CC * CC];
__device__ __nv_bfloat16 g_yh[(size_t)MM * CC];
__device__ __nv_bfloat16 g_yl[(size_t)MM * CC];

// ---------------- PTX helpers (all baseline compute_103-legal) -------------
__device__ __forceinline__ uint32_t smem_u32(const void* p) {
    uint32_t a;
    asm("{ .reg .u64 t; cvta.to.shared.u64 t, %1; cvt.u32.u64 %0, t; }"
        : "=r"(a) : "l"(p));
    return a;
}
__device__ __forceinline__ void cp16(uint32_t s, const void* g) {
    asm volatile("cp.async.cg.shared.global [%0], [%1], 16;"
                 :: "r"(s), "l"(g) : "memory");
}
__device__ __forceinline__ void cp_commit() {
    asm volatile("cp.async.commit_group;" ::: "memory");
}
template <int N>
__device__ __forceinline__ void cp_wait() {
    asm volatile("cp.async.wait_group %0;" :: "n"(N) : "memory");
}
__device__ __forceinline__ void ldm_x4(uint32_t* r, uint32_t a) {
    asm volatile("ldmatrix.sync.aligned.m8n8.x4.shared.b16 {%0,%1,%2,%3}, [%4];"
                 : "=r"(r[0]), "=r"(r[1]), "=r"(r[2]), "=r"(r[3]) : "r"(a));
}
__device__ __forceinline__ void ldm_x2(uint32_t* r, uint32_t a) {
    asm volatile("ldmatrix.sync.aligned.m8n8.x2.shared.b16 {%0,%1}, [%2];"
                 : "=r"(r[0]), "=r"(r[1]) : "r"(a));
}
__device__ __forceinline__ void mma16816(float* c, const uint32_t* a, const uint32_t* b) {
    asm volatile(
        "mma.sync.aligned.m16n8k16.row.col.f32.bf16.bf16.f32 "
        "{%0,%1,%2,%3}, {%4,%5,%6,%7}, {%8,%9}, {%0,%1,%2,%3};"
        : "+f"(c[0]), "+f"(c[1]), "+f"(c[2]), "+f"(c[3])
        : "r"(a[0]), "r"(a[1]), "r"(a[2]), "r"(a[3]), "r"(b[0]), "r"(b[1]));
}

// ---------------------------------------------------------------------------
// Conversion: fp32 -> (hi,lo) bf16 split
// ---------------------------------------------------------------------------
__global__ void convert_hl(const float* __restrict__ X,
                           __nv_bfloat16* __restrict__ H,
                           __nv_bfloat16* __restrict__ L) {
    int i = (blockIdx.x * blockDim.x + threadIdx.x) * 4;
    float4 v = *(const float4*)(X + i);
    float a[4] = {v.x, v.y, v.z, v.w};
    __nv_bfloat16 h[4], l[4];
#pragma unroll
    for (int j = 0; j < 4; j++) {
        h[j] = __float2bfloat16(a[j]);
        l[j] = __float2bfloat16(a[j] - __bfloat162float(h[j]));
    }
    *(__nv_bfloat162*)(H + i)     = __nv_bfloat162(h[0], h[1]);
    *(__nv_bfloat162*)(H + i + 2) = __nv_bfloat162(h[2], h[3]);
    *(__nv_bfloat162*)(L + i)     = __nv_bfloat162(l[0], l[1]);
    *(__nv_bfloat162*)(L + i + 2) = __nv_bfloat162(l[2], l[3]);
}

// W [K,N] row-major -> Wt [N,K] hi/lo bf16
__global__ void transpose_convert(const float* __restrict__ W,
                                  __nv_bfloat16* __restrict__ Th,
                                  __nv_bfloat16* __restrict__ Tl,
                                  int K, int N) {
    __shared__ float t[32][33];
    int k0 = blockIdx.y * 32, n0 = blockIdx.x * 32;
    int tx = threadIdx.x, ty = threadIdx.y; // 32 x 8
#pragma unroll
    for (int i = 0; i < 32; i += 8)
        t[ty + i][tx] = W[(size_t)(k0 + ty + i) * N + n0 + tx];
    __syncthreads();
#pragma unroll
    for (int i = 0; i < 32; i += 8) {
        float v = t[tx][ty + i];
        __nv_bfloat16 h = __float2bfloat16(v);
        __nv_bfloat16 l = __float2bfloat16(v - __bfloat162float(h));
        size_t o = (size_t)(n0 + ty + i) * K + k0 + tx;
        Th[o] = h; Tl[o] = l;
    }
}

// ---------------------------------------------------------------------------
// HMMA bf16x3 GEMM: C[M,N] fp32 = (Ah+Al)[M,K] @ (Bh+Bl)[N,K]^T
// 128x128 tile, 256 threads (2x4 warps, 64x32 each), BK=32, double-buffered
// cp.async. SMEM rows padded to 80B (conflict-free ldmatrix).
// ---------------------------------------------------------------------------
#define BK 32
#define RSB 80                      // bytes per SMEM row (32 bf16 + 8 pad)
#define TILE_BYTES (128 * RSB)      // 10240
#define OFF_AH 0
#define OFF_AL (1 * TILE_BYTES)
#define OFF_BH (2 * TILE_BYTES)
#define OFF_BL (3 * TILE_BYTES)
#define STAGE_BYTES (4 * TILE_BYTES)        // 40960
#define GEMM_SMEM (2 * STAGE_BYTES)         // 81920

__global__ __launch_bounds__(256) void gemm_hmma(
    const __nv_bfloat16* __restrict__ Ah, const __nv_bfloat16* __restrict__ Al,
    const __nv_bfloat16* __restrict__ Bh, const __nv_bfloat16* __restrict__ Bl,
    float* __restrict__ C, int M, int N, int K)
{
    extern __shared__ __align__(128) char smem[];
    const uint32_t sb = smem_u32(smem);
    const int tid  = threadIdx.x;
    const int wid  = tid >> 5;
    const int lane = tid & 31;
    const int wm   = wid & 1;      // 0..1  (M dir, 64 rows each)
    const int wn   = wid >> 1;     // 0..3  (N dir, 32 cols each)
    const int bm   = blockIdx.y * 128;
    const int bn   = blockIdx.x * 128;

    const __nv_bfloat16* ah = Ah + (size_t)bm * K;
    const __nv_bfloat16* al = Al + (size_t)bm * K;
    const __nv_bfloat16* bh = Bh + (size_t)bn * K;
    const __nv_bfloat16* bl = Bl + (size_t)bn * K;

    float acc[4][4][4];
#pragma unroll
    for (int i = 0; i < 4; i++)
#pragma unroll
        for (int j = 0; j < 4; j++)
#pragma unroll
            for (int k = 0; k < 4; k++) acc[i][j][k] = 0.f;

    // this thread's two load slots per tile: chunks tid and tid+256
    const int r0 = tid >> 2, c0 = tid & 3;           // chunk tid
    const int r1 = (tid + 256) >> 2, c1 = tid & 3;   // chunk tid+256

    auto load_stage = [&](int buf, int k0) {
        const uint32_t s = sb + buf * STAGE_BYTES;
        const uint32_t so0 = r0 * RSB + c0 * 16;
        const uint32_t so1 = r1 * RSB + c1 * 16;
        const size_t go0 = (size_t)r0 * K + k0 + c0 * 8;
        const size_t go1 = (size_t)r1 * K + k0 + c1 * 8;
        cp16(s + OFF_AH + so0, ah + go0);  cp16(s + OFF_AH + so1, ah + go1);
        cp16(s + OFF_AL + so0, al + go0);  cp16(s + OFF_AL + so1, al + go1);
        cp16(s + OFF_BH + so0, bh + go0);  cp16(s + OFF_BH + so1, bh + go1);
        cp16(s + OFF_BL + so0, bl + go0);  cp16(s + OFF_BL + so1, bl + go1);
    };

    // precomputed ldmatrix lane addressing
    const int tb = lane & 15;
    const uint32_t b_row  = wn * 32 + (tb & 7);        // + ni*8
    const uint32_t b_chnk = (uint32_t)(tb >> 3);       // + ks*2
    const uint32_t a_row  = wm * 64 + (lane & 7) + ((lane >> 3) & 1) * 8; // + mi*16
    const uint32_t a_chnk = (uint32_t)(lane >> 4);     // + ks*2

    load_stage(0, 0);
    cp_commit();

    const int NCH = K / BK;
    for (int ch = 0; ch < NCH; ch++) {
        const int buf = ch & 1;
        if (ch + 1 < NCH) {
            load_stage(buf ^ 1, (ch + 1) * BK);
            cp_commit();
            cp_wait<1>();
        } else {
            cp_wait<0>();
        }
        __syncthreads();

        const uint32_t s = sb + buf * STAGE_BYTES;
#pragma unroll
        for (int ks = 0; ks < 2; ks++) {
            uint32_t bfh[4][2], bfl[4][2];
#pragma unroll
            for (int ni = 0; ni < 4; ni++) {
                uint32_t ba = s + (b_row + ni * 8) * RSB + (b_chnk + ks * 2) * 16;
                ldm_x2(bfh[ni], ba + OFF_BH);
                ldm_x2(bfl[ni], ba + OFF_BL);
            }
#pragma unroll
            for (int mi = 0; mi < 4; mi++) {
                uint32_t aa = s + (a_row + mi * 16) * RSB + (a_chnk + ks * 2) * 16;
                uint32_t afh[4], afl[4];
                ldm_x4(afh, aa + OFF_AH);
                ldm_x4(afl, aa + OFF_AL);
#pragma unroll
                for (int ni = 0; ni < 4; ni++) {
                    mma16816(acc[mi][ni], afh, bfh[ni]);
                    mma16816(acc[mi][ni], afh, bfl[ni]);
                    mma16816(acc[mi][ni], afl, bfh[ni]);
                }
            }
        }
        __syncthreads();
    }

    // epilogue: c0,c1 -> (row g, col 2q), c2,c3 -> (row g+8)
    const int g = lane >> 2, q = lane & 3;
#pragma unroll
    for (int mi = 0; mi < 4; mi++) {
        const int row = bm + wm * 64 + mi * 16 + g;
#pragma unroll
        for (int ni = 0; ni < 4; ni++) {
            const int col = bn + wn * 32 + ni * 8 + q * 2;
            float* cp0 = C + (size_t)row * N + col;
            float* cp1 = C + (size_t)(row + 8) * N + col;
            *(float2*)cp0 = make_float2(acc[mi][ni][0], acc[mi][ni][1]);
            *(float2*)cp1 = make_float2(acc[mi][ni][2], acc[mi][ni][3]);
        }
    }
}

// ---------------------------------------------------------------------------
// Causal flash-attention, fp32 (reference window term is dead code).
// Writes bf16 hi/lo split directly for the projection GEMM.
// ---------------------------------------------------------------------------
#define TQ 128
#define TK 32

__global__ __launch_bounds__(128) void attn_kernel(
    const float* __restrict__ qkv,
    __nv_bfloat16* __restrict__ yh, __nv_bfloat16* __restrict__ yl)
{
    __shared__ float Ks[TK][DD];
    __shared__ float Vs[TK][DD];
    __shared__ float Sc[TQ][TK + 1];

    const int bh = blockIdx.x;
    const int b  = bh >> 4;
    const int h  = bh & 15;
    const int rt = gridDim.y - 1 - blockIdx.y;
    const int r0 = rt * TQ;
    const int tid = threadIdx.x;
    const int r   = r0 + tid;

    const float* base = qkv + (size_t)b * TT * C3;
    const float scale = 0.125f;

    float q[DD];
    {
        const float* qp = base + (size_t)r * C3 + h * DD;
#pragma unroll
        for (int d = 0; d < DD; d += 4) {
            float4 v = *(const float4*)(qp + d);
            q[d] = v.x * scale; q[d+1] = v.y * scale;
            q[d+2] = v.z * scale; q[d+3] = v.w * scale;
        }
    }

    float acc[DD];
#pragma unroll
    for (int d = 0; d < DD; d++) acc[d] = 0.f;
    float m = -1e30f, l = 0.f;

    const float* kbase = base + CC + h * DD;
    const float* vbase = base + 2 * CC + h * DD;

    const int kend = r0 + TQ;
    for (int k0 = 0; k0 < kend; k0 += TK) {
#pragma unroll
        for (int i = 0; i < 4; i++) {
            int f   = i * 128 + tid;
            int row = f >> 4;
            int col = (f & 15) * 4;
            size_t goff = (size_t)(k0 + row) * C3 + col;
            *(float4*)&Ks[row][col] = *(const float4*)(kbase + goff);
            *(float4*)&Vs[row][col] = *(const float4*)(vbase + goff);
        }
        __syncthreads();

        float tmax = -1e30f;
#pragma unroll 4
        for (int s = 0; s < TK; s++) {
            float sum = 0.f;
#pragma unroll
            for (int d = 0; d < DD; d += 4) {
                float4 kv = *(const float4*)&Ks[s][d];
                sum += q[d] * kv.x + q[d+1] * kv.y
                     + q[d+2] * kv.z + q[d+3] * kv.w;
            }
            sum = ((k0 + s) <= r) ? sum : -1e30f;
            Sc[tid][s] = sum;
            tmax = fmaxf(tmax, sum);
        }

        float mnew = fmaxf(m, tmax);
        float corr = __expf(m - mnew);
        l *= corr;
#pragma unroll
        for (int d = 0; d < DD; d++) acc[d] *= corr;

#pragma unroll 4
        for (int s = 0; s < TK; s++) {
            float p = __expf(Sc[tid][s] - mnew);
            l += p;
#pragma unroll
            for (int d = 0; d < DD; d += 4) {
                float4 vv = *(const float4*)&Vs[s][d];
                acc[d]   += p * vv.x; acc[d+1] += p * vv.y;
                acc[d+2] += p * vv.z; acc[d+3] += p * vv.w;
            }
        }
        m = mnew;
        __syncthreads();
    }

    float inv = 1.f / l;
    size_t o = ((size_t)b * TT + r) * CC + h * DD;
#pragma unroll
    for (int d = 0; d < DD; d += 2) {
        float v0 = acc[d] * inv, v1 = acc[d+1] * inv;
        __nv_bfloat16 h0 = __float2bfloat16(v0);
        __nv_bfloat16 h1 = __float2bfloat16(v1);
        __nv_bfloat16 l0 = __float2bfloat16(v0 - __bfloat162float(h0));
        __nv_bfloat16 l1 = __float2bfloat16(v1 - __bfloat162float(h1));
        *(__nv_bfloat162*)(yh + o + d) = __nv_bfloat162(h0, h1);
        *(__nv_bfloat162*)(yl + o + d) = __nv_bfloat162(l0, l1);
    }
}

// ---------------------------------------------------------------------------
extern "C" void kernel_launch(void* const* d_in, const int* in_sizes, int n_in,
                              void* d_out, int out_size)
{
    const float* x      = (const float*)d_in[0];
    const float* w_qkv  = (const float*)d_in[1];
    const float* w_proj = (const float*)d_in[2];
    float* out = (float*)d_out;

    void *pqkv, *pxh, *pxl, *pwqh, *pwql, *pwph, *pwpl, *pyh, *pyl;
    cudaGetSymbolAddress(&pqkv, g_qkv);
    cudaGetSymbolAddress(&pxh, g_xh);   cudaGetSymbolAddress(&pxl, g_xl);
    cudaGetSymbolAddress(&pwqh, g_wqkvT_h); cudaGetSymbolAddress(&pwql, g_wqkvT_l);
    cudaGetSymbolAddress(&pwph, g_wprojT_h); cudaGetSymbolAddress(&pwpl, g_wprojT_l);
    cudaGetSymbolAddress(&pyh, g_yh);   cudaGetSymbolAddress(&pyl, g_yl);

    // no static guard (determinism rule) — cheap, idempotent
    cudaFuncSetAttribute(gemm_hmma,
                         cudaFuncAttributeMaxDynamicSharedMemorySize, GEMM_SMEM);

    // 1) split-convert x; transpose+split both weight matrices
    convert_hl<<<(MM * CC) / (256 * 4), 256>>>(x, (__nv_bfloat16*)pxh, (__nv_bfloat16*)pxl);
    dim3 tcb(32, 8);
    transpose_convert<<<dim3(C3 / 32, CC / 32), tcb>>>(w_qkv,
        (__nv_bfloat16*)pwqh, (__nv_bfloat16*)pwql, CC, C3);
    transpose_convert<<<dim3(CC / 32, CC / 32), tcb>>>(w_proj,
        (__nv_bfloat16*)pwph, (__nv_bfloat16*)pwpl, CC, CC);

    // 2) QKV GEMM: [4096,1024] x [1024,3072] -> fp32 qkv
    gemm_hmma<<<dim3(C3 / 128, MM / 128), 256, GEMM_SMEM>>>(
        (const __nv_bfloat16*)pxh, (const __nv_bfloat16*)pxl,
        (const __nv_bfloat16*)pwqh, (const __nv_bfloat16*)pwql,
        (float*)pqkv, MM, C3, CC);

    // 3) causal attention (writes bf16 hi/lo directly)
    attn_kernel<<<dim3(BB * HH, TT / TQ), 128>>>(
        (const float*)pqkv, (__nv_bfloat16*)pyh, (__nv_bfloat16*)pyl);

    // 4) projection GEMM: [4096,1024] x [1024,1024] -> out
    gemm_hmma<<<dim3(CC / 128, MM / 128), 256, GEMM_SMEM>>>(
        (const __nv_bfloat16*)pyh, (const __nv_bfloat16*)pyl,
        (const __nv_bfloat16*)pwph, (const __nv_bfloat16*)pwpl,
        out, MM, CC, CC);
}

// round 7
// speedup vs baseline: 2.9972x; 1.9591x over previous
#include <cuda_runtime.h>
#include <cuda_bf16.h>
#include <math.h>
#include <stdint.h>

#define BB 2
#define TT 2048
#define CC 1024
#define HH 16
#define DD 64
#define C3 (3*CC)
#define MM (BB*TT)   // 4096

// ---------------- scratch (__device__ globals; allocation-free rule) -------
__device__ __nv_bfloat16 g_qkvh[(size_t)MM * C3];      // qkv hi [4096,3072]
__device__ __nv_bfloat16 g_qkvl[(size_t)MM * C3];      // qkv lo
__device__ __nv_bfloat16 g_xh[(size_t)MM * CC];
__device__ __nv_bfloat16 g_xl[(size_t)MM * CC];
__device__ __nv_bfloat16 g_wqkvT_h[(size_t)C3 * CC];   // w_qkv^T [3072,1024]
__device__ __nv_bfloat16 g_wqkvT_l[(size_t)C3 * CC];
__device__ __nv_bfloat16 g_wprojT_h[(size_t)CC * CC];  // w_proj^T [1024,1024]
__device__ __nv_bfloat16 g_wprojT_l[(size_t)CC * CC];
__device__ __nv_bfloat16 g_yh[(size_t)MM * CC];
__device__ __nv_bfloat16 g_yl[(size_t)MM * CC];

// ---------------- PTX helpers (baseline compute_103-legal) -----------------
__device__ __forceinline__ uint32_t smem_u32(const void* p) {
    uint32_t a;
    asm("{ .reg .u64 t; cvta.to.shared.u64 t, %1; cvt.u32.u64 %0, t; }"
        : "=r"(a) : "l"(p));
    return a;
}
__device__ __forceinline__ void cp16(uint32_t s, const void* g) {
    asm volatile("cp.async.cg.shared.global [%0], [%1], 16;"
                 :: "r"(s), "l"(g) : "memory");
}
__device__ __forceinline__ void cp_commit() {
    asm volatile("cp.async.commit_group;" ::: "memory");
}
template <int N>
__device__ __forceinline__ void cp_wait() {
    asm volatile("cp.async.wait_group %0;" :: "n"(N) : "memory");
}
__device__ __forceinline__ void ldm_x4(uint32_t* r, uint32_t a) {
    asm volatile("ldmatrix.sync.aligned.m8n8.x4.shared.b16 {%0,%1,%2,%3}, [%4];"
                 : "=r"(r[0]), "=r"(r[1]), "=r"(r[2]), "=r"(r[3]) : "r"(a));
}
__device__ __forceinline__ void ldm_x4_t(uint32_t* r, uint32_t a) {
    asm volatile("ldmatrix.sync.aligned.m8n8.x4.trans.shared.b16 {%0,%1,%2,%3}, [%4];"
                 : "=r"(r[0]), "=r"(r[1]), "=r"(r[2]), "=r"(r[3]) : "r"(a));
}
__device__ __forceinline__ void ldm_x2(uint32_t* r, uint32_t a) {
    asm volatile("ldmatrix.sync.aligned.m8n8.x2.shared.b16 {%0,%1}, [%2];"
                 : "=r"(r[0]), "=r"(r[1]) : "r"(a));
}
__device__ __forceinline__ void mma16816(float* c, const uint32_t* a, const uint32_t* b) {
    asm volatile(
        "mma.sync.aligned.m16n8k16.row.col.f32.bf16.bf16.f32 "
        "{%0,%1,%2,%3}, {%4,%5,%6,%7}, {%8,%9}, {%0,%1,%2,%3};"
        : "+f"(c[0]), "+f"(c[1]), "+f"(c[2]), "+f"(c[3])
        : "r"(a[0]), "r"(a[1]), "r"(a[2]), "r"(a[3]), "r"(b[0]), "r"(b[1]));
}
__device__ __forceinline__ void split_pack2(float a, float b, uint32_t& hi, uint32_t& lo) {
    __nv_bfloat16 ha = __float2bfloat16(a), hb = __float2bfloat16(b);
    __nv_bfloat16 la = __float2bfloat16(a - __bfloat162float(ha));
    __nv_bfloat16 lb = __float2bfloat16(b - __bfloat162float(hb));
    __nv_bfloat162 H(ha, hb), L(la, lb);
    hi = *(uint32_t*)&H; lo = *(uint32_t*)&L;
}

// ---------------------------------------------------------------------------
// Conversions
// ---------------------------------------------------------------------------
__global__ void convert_hl(const float* __restrict__ X,
                           __nv_bfloat16* __restrict__ H,
                           __nv_bfloat16* __restrict__ L) {
    int i = (blockIdx.x * blockDim.x + threadIdx.x) * 4;
    float4 v = *(const float4*)(X + i);
    float a[4] = {v.x, v.y, v.z, v.w};
    __nv_bfloat16 h[4], l[4];
#pragma unroll
    for (int j = 0; j < 4; j++) {
        h[j] = __float2bfloat16(a[j]);
        l[j] = __float2bfloat16(a[j] - __bfloat162float(h[j]));
    }
    *(__nv_bfloat162*)(H + i)     = __nv_bfloat162(h[0], h[1]);
    *(__nv_bfloat162*)(H + i + 2) = __nv_bfloat162(h[2], h[3]);
    *(__nv_bfloat162*)(L + i)     = __nv_bfloat162(l[0], l[1]);
    *(__nv_bfloat162*)(L + i + 2) = __nv_bfloat162(l[2], l[3]);
}

__global__ void transpose_convert(const float* __restrict__ W,
                                  __nv_bfloat16* __restrict__ Th,
                                  __nv_bfloat16* __restrict__ Tl,
                                  int K, int N) {
    __shared__ float t[32][33];
    int k0 = blockIdx.y * 32, n0 = blockIdx.x * 32;
    int tx = threadIdx.x, ty = threadIdx.y;
#pragma unroll
    for (int i = 0; i < 32; i += 8)
        t[ty + i][tx] = W[(size_t)(k0 + ty + i) * N + n0 + tx];
    __syncthreads();
#pragma unroll
    for (int i = 0; i < 32; i += 8) {
        float v = t[tx][ty + i];
        __nv_bfloat16 h = __float2bfloat16(v);
        __nv_bfloat16 l = __float2bfloat16(v - __bfloat162float(h));
        size_t o = (size_t)(n0 + ty + i) * K + k0 + tx;
        Th[o] = h; Tl[o] = l;
    }
}

// ---------------------------------------------------------------------------
// HMMA bf16x3 GEMM (templated epilogue: fp32 C or hi/lo bf16 split)
// ---------------------------------------------------------------------------
#define BK 32
#define RSB 80
#define TILE_BYTES (128 * RSB)
#define OFF_AH 0
#define OFF_AL (1 * TILE_BYTES)
#define OFF_BH (2 * TILE_BYTES)
#define OFF_BL (3 * TILE_BYTES)
#define STAGE_BYTES (4 * TILE_BYTES)
#define GEMM_SMEM (2 * STAGE_BYTES)

template <bool SPLIT>
__global__ __launch_bounds__(256) void gemm_hmma(
    const __nv_bfloat16* __restrict__ Ah, const __nv_bfloat16* __restrict__ Al,
    const __nv_bfloat16* __restrict__ Bh, const __nv_bfloat16* __restrict__ Bl,
    float* __restrict__ C, __nv_bfloat16* __restrict__ Ch,
    __nv_bfloat16* __restrict__ Cl, int M, int N, int K)
{
    extern __shared__ __align__(128) char smem[];
    const uint32_t sb = smem_u32(smem);
    const int tid  = threadIdx.x;
    const int wid  = tid >> 5;
    const int lane = tid & 31;
    const int wm   = wid & 1;
    const int wn   = wid >> 1;
    const int bm   = blockIdx.y * 128;
    const int bn   = blockIdx.x * 128;

    const __nv_bfloat16* ah = Ah + (size_t)bm * K;
    const __nv_bfloat16* al = Al + (size_t)bm * K;
    const __nv_bfloat16* bh = Bh + (size_t)bn * K;
    const __nv_bfloat16* bl = Bl + (size_t)bn * K;

    float acc[4][4][4];
#pragma unroll
    for (int i = 0; i < 4; i++)
#pragma unroll
        for (int j = 0; j < 4; j++)
#pragma unroll
            for (int k = 0; k < 4; k++) acc[i][j][k] = 0.f;

    const int r0 = tid >> 2, c0 = tid & 3;
    const int r1 = (tid + 256) >> 2, c1 = tid & 3;

    auto load_stage = [&](int buf, int k0) {
        const uint32_t s = sb + buf * STAGE_BYTES;
        const uint32_t so0 = r0 * RSB + c0 * 16;
        const uint32_t so1 = r1 * RSB + c1 * 16;
        const size_t go0 = (size_t)r0 * K + k0 + c0 * 8;
        const size_t go1 = (size_t)r1 * K + k0 + c1 * 8;
        cp16(s + OFF_AH + so0, ah + go0);  cp16(s + OFF_AH + so1, ah + go1);
        cp16(s + OFF_AL + so0, al + go0);  cp16(s + OFF_AL + so1, al + go1);
        cp16(s + OFF_BH + so0, bh + go0);  cp16(s + OFF_BH + so1, bh + go1);
        cp16(s + OFF_BL + so0, bl + go0);  cp16(s + OFF_BL + so1, bl + go1);
    };

    const int tb = lane & 15;
    const uint32_t b_row  = wn * 32 + (tb & 7);
    const uint32_t b_chnk = (uint32_t)(tb >> 3);
    const uint32_t a_row  = wm * 64 + (lane & 7) + ((lane >> 3) & 1) * 8;
    const uint32_t a_chnk = (uint32_t)(lane >> 4);

    load_stage(0, 0);
    cp_commit();

    const int NCH = K / BK;
    for (int ch = 0; ch < NCH; ch++) {
        const int buf = ch & 1;
        if (ch + 1 < NCH) {
            load_stage(buf ^ 1, (ch + 1) * BK);
            cp_commit();
            cp_wait<1>();
        } else {
            cp_wait<0>();
        }
        __syncthreads();

        const uint32_t s = sb + buf * STAGE_BYTES;
#pragma unroll
        for (int ks = 0; ks < 2; ks++) {
            uint32_t bfh[4][2], bfl[4][2];
#pragma unroll
            for (int ni = 0; ni < 4; ni++) {
                uint32_t ba = s + (b_row + ni * 8) * RSB + (b_chnk + ks * 2) * 16;
                ldm_x2(bfh[ni], ba + OFF_BH);
                ldm_x2(bfl[ni], ba + OFF_BL);
            }
#pragma unroll
            for (int mi = 0; mi < 4; mi++) {
                uint32_t aa = s + (a_row + mi * 16) * RSB + (a_chnk + ks * 2) * 16;
                uint32_t afh[4], afl[4];
                ldm_x4(afh, aa + OFF_AH);
                ldm_x4(afl, aa + OFF_AL);
#pragma unroll
                for (int ni = 0; ni < 4; ni++) {
                    mma16816(acc[mi][ni], afh, bfh[ni]);
                    mma16816(acc[mi][ni], afh, bfl[ni]);
                    mma16816(acc[mi][ni], afl, bfh[ni]);
                }
            }
        }
        __syncthreads();
    }

    const int g = lane >> 2, q = lane & 3;
#pragma unroll
    for (int mi = 0; mi < 4; mi++) {
        const int row = bm + wm * 64 + mi * 16 + g;
#pragma unroll
        for (int ni = 0; ni < 4; ni++) {
            const int col = bn + wn * 32 + ni * 8 + q * 2;
            if (SPLIT) {
                uint32_t h0, l0, h1, l1;
                split_pack2(acc[mi][ni][0], acc[mi][ni][1], h0, l0);
                split_pack2(acc[mi][ni][2], acc[mi][ni][3], h1, l1);
                size_t o0 = (size_t)row * N + col;
                size_t o1 = (size_t)(row + 8) * N + col;
                *(uint32_t*)(Ch + o0) = h0; *(uint32_t*)(Cl + o0) = l0;
                *(uint32_t*)(Ch + o1) = h1; *(uint32_t*)(Cl + o1) = l1;
            } else {
                float* cp0 = C + (size_t)row * N + col;
                float* cp1 = C + (size_t)(row + 8) * N + col;
                *(float2*)cp0 = make_float2(acc[mi][ni][0], acc[mi][ni][1]);
                *(float2*)cp1 = make_float2(acc[mi][ni][2], acc[mi][ni][3]);
            }
        }
    }
}

// ---------------------------------------------------------------------------
// HMMA flash attention (causal; reference window term is dead code).
// 8 warps x 16 query rows = 128 queries/CTA; key tiles of 64.
// S = (Qh+Ql)(Kh+Kl)^T and O = (Ph+Pl)(Vh+Vl), each via 3 HMMA products.
// ---------------------------------------------------------------------------
#define AROW 144                       // smem row bytes: 64 bf16 + 16 pad
#define A_OQH 0
#define A_OQL (128 * AROW)             // 18432
#define A_STG (2 * 128 * AROW)         // 36864
#define A_TILE (64 * AROW)             // 9216
#define A_STAGE_BYTES (4 * A_TILE)     // 36864
#define ATT_SMEM (A_STG + 2 * A_STAGE_BYTES)   // 110592

__global__ __launch_bounds__(256) void attn_hmma(
    const __nv_bfloat16* __restrict__ qh, const __nv_bfloat16* __restrict__ ql,
    __nv_bfloat16* __restrict__ yh, __nv_bfloat16* __restrict__ yl)
{
    extern __shared__ __align__(128) char smem[];
    const uint32_t sb = smem_u32(smem);
    const int tid = threadIdx.x, lane = tid & 31, w = tid >> 5;
    const int bh = blockIdx.x, b = bh >> 4, h = bh & 15;
    const int rt = gridDim.y - 1 - blockIdx.y;    // heavy row-tiles first
    const int r0 = rt * 128;
    const int wq0 = r0 + w * 16;

    // ---- Q tile load (hi+lo), own commit group ----
    {
        const int qt = tid >> 7;                  // 0: hi, 1: lo
        const __nv_bfloat16* src = qt ? ql : qh;
        const uint32_t dst = sb + (qt ? A_OQL : A_OQH);
#pragma unroll
        for (int j = 0; j < 8; j++) {
            int idx = (tid & 127) + j * 128;
            int row = idx >> 3, col = idx & 7;
            cp16(dst + row * AROW + col * 16,
                 src + ((size_t)(b * TT + r0 + row)) * C3 + h * DD + col * 8);
        }
    }
    cp_commit();

    // ---- K/V stage loader ----
    auto load_stage = [&](int buf, int k0) {
        const int t4 = tid >> 6;                  // 0:KH 1:KL 2:VH 3:VL
        const __nv_bfloat16* src = (t4 & 1) ? ql : qh;
        const int voff = (t4 >> 1) ? 2 * CC : CC;
        const uint32_t dst = sb + A_STG + buf * A_STAGE_BYTES + t4 * A_TILE;
#pragma unroll
        for (int j = 0; j < 8; j++) {
            int idx = (tid & 63) + j * 64;
            int row = idx >> 3, col = idx & 7;
            cp16(dst + row * AROW + col * 16,
                 src + ((size_t)(b * TT + k0 + row)) * C3 + voff + h * DD + col * 8);
        }
    };

    load_stage(0, 0);
    cp_commit();
    cp_wait<1>();          // Q done
    __syncthreads();

    // ---- Q fragments (register-resident across whole key loop) ----
    uint32_t qfh[4][4], qfl[4][4];
    {
        const uint32_t q_row = w * 16 + (lane & 7) + ((lane >> 3) & 1) * 8;
#pragma unroll
        for (int ks = 0; ks < 4; ks++) {
            uint32_t qa = sb + A_OQH + q_row * AROW + (ks * 2 + (lane >> 4)) * 16;
            ldm_x4(qfh[ks], qa);
            ldm_x4(qfl[ks], qa + A_OQL);
        }
    }

    float o[8][4];
#pragma unroll
    for (int i = 0; i < 8; i++)
#pragma unroll
        for (int j = 0; j < 4; j++) o[i][j] = 0.f;
    float m0 = -1e30f, m1 = -1e30f, l0 = 0.f, l1 = 0.f;

    const uint32_t k_row  = (lane & 7) + (lane >> 4) * 8;
    const uint32_t k_half = (lane >> 3) & 1;
    const uint32_t v_key  = lane & 15;
    const int rg0 = wq0 + (lane >> 2), rg1 = rg0 + 8;
    const int qq2 = (lane & 3) * 2;

    const int NT = 2 * rt + 2;
    for (int ch = 0; ch < NT; ch++) {
        const int buf = ch & 1;
        if (ch + 1 < NT) {
            load_stage(buf ^ 1, (ch + 1) * 64);
            cp_commit();
            cp_wait<1>();
        } else {
            cp_wait<0>();
        }
        __syncthreads();

        const int k0 = ch * 64;
        if (k0 <= wq0) {   // else fully masked for this warp: skip compute
            const uint32_t stg = sb + A_STG + buf * A_STAGE_BYTES;

            float s[8][4];
#pragma unroll
            for (int i = 0; i < 8; i++)
#pragma unroll
                for (int j = 0; j < 4; j++) s[i][j] = 0.f;

            // ---- S = Q K^T (3-product split) ----
#pragma unroll
            for (int ks = 0; ks < 4; ks++) {
#pragma unroll
                for (int np = 0; np < 4; np++) {
                    uint32_t ka = stg + (np * 16 + k_row) * AROW
                                + (ks * 2 + k_half) * 16;
                    uint32_t kh4[4], kl4[4];
                    ldm_x4(kh4, ka);               // K hi (tile 0)
                    ldm_x4(kl4, ka + A_TILE);      // K lo (tile 1)
                    mma16816(s[2*np],   qfh[ks], kh4);
                    mma16816(s[2*np],   qfh[ks], kl4);
                    mma16816(s[2*np],   qfl[ks], kh4);
                    mma16816(s[2*np+1], qfh[ks], kh4 + 2);
                    mma16816(s[2*np+1], qfh[ks], kl4 + 2);
                    mma16816(s[2*np+1], qfl[ks], kh4 + 2);
                }
            }

            // ---- scale + causal mask ----
            const bool need_mask = (wq0 - k0) < 64;
#pragma unroll
            for (int ni = 0; ni < 8; ni++) {
                int col = k0 + ni * 8 + qq2;
                float v0 = s[ni][0] * 0.125f, v1 = s[ni][1] * 0.125f;
                float v2 = s[ni][2] * 0.125f, v3 = s[ni][3] * 0.125f;
                if (need_mask) {
                    if (col     > rg0) v0 = -1e30f;
                    if (col + 1 > rg0) v1 = -1e30f;
                    if (col     > rg1) v2 = -1e30f;
                    if (col + 1 > rg1) v3 = -1e30f;
                }
                s[ni][0] = v0; s[ni][1] = v1; s[ni][2] = v2; s[ni][3] = v3;
            }

            // ---- online softmax (rows g and g+8, quad-reduced) ----
            float mx0 = -1e30f, mx1 = -1e30f;
#pragma unroll
            for (int ni = 0; ni < 8; ni++) {
                mx0 = fmaxf(mx0, fmaxf(s[ni][0], s[ni][1]));
                mx1 = fmaxf(mx1, fmaxf(s[ni][2], s[ni][3]));
            }
            mx0 = fmaxf(mx0, __shfl_xor_sync(0xffffffffu, mx0, 1));
            mx0 = fmaxf(mx0, __shfl_xor_sync(0xffffffffu, mx0, 2));
            mx1 = fmaxf(mx1, __shfl_xor_sync(0xffffffffu, mx1, 1));
            mx1 = fmaxf(mx1, __shfl_xor_sync(0xffffffffu, mx1, 2));

            float nm0 = fmaxf(m0, mx0), nm1 = fmaxf(m1, mx1);
            float cr0 = __expf(m0 - nm0), cr1 = __expf(m1 - nm1);
            float ps0 = 0.f, ps1 = 0.f;
#pragma unroll
            for (int ni = 0; ni < 8; ni++) {
                s[ni][0] = __expf(s[ni][0] - nm0);
                s[ni][1] = __expf(s[ni][1] - nm0);
                s[ni][2] = __expf(s[ni][2] - nm1);
                s[ni][3] = __expf(s[ni][3] - nm1);
                ps0 += s[ni][0] + s[ni][1];
                ps1 += s[ni][2] + s[ni][3];
            }
            ps0 += __shfl_xor_sync(0xffffffffu, ps0, 1);
            ps0 += __shfl_xor_sync(0xffffffffu, ps0, 2);
            ps1 += __shfl_xor_sync(0xffffffffu, ps1, 1);
            ps1 += __shfl_xor_sync(0xffffffffu, ps1, 2);
            l0 = l0 * cr0 + ps0;  l1 = l1 * cr1 + ps1;
            m0 = nm0;  m1 = nm1;
#pragma unroll
            for (int nd = 0; nd < 8; nd++) {
                o[nd][0] *= cr0; o[nd][1] *= cr0;
                o[nd][2] *= cr1; o[nd][3] *= cr1;
            }

            // ---- O += P V (3-product split); P frags direct from S regs ----
#pragma unroll
            for (int ks = 0; ks < 4; ks++) {
                uint32_t ah[4], al[4];
                split_pack2(s[2*ks][0],   s[2*ks][1],   ah[0], al[0]);
                split_pack2(s[2*ks][2],   s[2*ks][3],   ah[1], al[1]);
                split_pack2(s[2*ks+1][0], s[2*ks+1][1], ah[2], al[2]);
                split_pack2(s[2*ks+1][2], s[2*ks+1][3], ah[3], al[3]);
#pragma unroll
                for (int np = 0; np < 4; np++) {
                    uint32_t va = stg + 2 * A_TILE + (ks * 16 + v_key) * AROW
                                + (np * 2 + (lane >> 4)) * 16;
                    uint32_t vh4[4], vl4[4];
                    ldm_x4_t(vh4, va);             // V hi (tile 2)
                    ldm_x4_t(vl4, va + A_TILE);    // V lo (tile 3)
                    mma16816(o[2*np],   ah, vh4);
                    mma16816(o[2*np],   ah, vl4);
                    mma16816(o[2*np],   al, vh4);
                    mma16816(o[2*np+1], ah, vh4 + 2);
                    mma16816(o[2*np+1], ah, vl4 + 2);
                    mma16816(o[2*np+1], al, vh4 + 2);
                }
            }
        }
        __syncthreads();
    }

    // ---- epilogue: O / l, hi/lo bf16 store ----
    const float i0 = 1.f / l0, i1 = 1.f / l1;
    const size_t ob = ((size_t)(b * TT + rg0)) * CC + h * DD + qq2;
#pragma unroll
    for (int nd = 0; nd < 8; nd++) {
        uint32_t h0, lo0, h1, lo1;
        split_pack2(o[nd][0] * i0, o[nd][1] * i0, h0, lo0);
        split_pack2(o[nd][2] * i1, o[nd][3] * i1, h1, lo1);
        *(uint32_t*)(yh + ob + nd * 8) = h0;
        *(uint32_t*)(yl + ob + nd * 8) = lo0;
        *(uint32_t*)(yh + ob + 8 * CC + nd * 8) = h1;
        *(uint32_t*)(yl + ob + 8 * CC + nd * 8) = lo1;
    }
}

// ---------------------------------------------------------------------------
extern "C" void kernel_launch(void* const* d_in, const int* in_sizes, int n_in,
                              void* d_out, int out_size)
{
    const float* x      = (const float*)d_in[0];
    const float* w_qkv  = (const float*)d_in[1];
    const float* w_proj = (const float*)d_in[2];
    float* out = (float*)d_out;

    void *pqh, *pql, *pxh, *pxl, *pwqh, *pwql, *pwph, *pwpl, *pyh, *pyl;
    cudaGetSymbolAddress(&pqh, g_qkvh); cudaGetSymbolAddress(&pql, g_qkvl);
    cudaGetSymbolAddress(&pxh, g_xh);   cudaGetSymbolAddress(&pxl, g_xl);
    cudaGetSymbolAddress(&pwqh, g_wqkvT_h); cudaGetSymbolAddress(&pwql, g_wqkvT_l);
    cudaGetSymbolAddress(&pwph, g_wprojT_h); cudaGetSymbolAddress(&pwpl, g_wprojT_l);
    cudaGetSymbolAddress(&pyh, g_yh);   cudaGetSymbolAddress(&pyl, g_yl);

    cudaFuncSetAttribute(gemm_hmma<true>,
                         cudaFuncAttributeMaxDynamicSharedMemorySize, GEMM_SMEM);
    cudaFuncSetAttribute(gemm_hmma<false>,
                         cudaFuncAttributeMaxDynamicSharedMemorySize, GEMM_SMEM);
    cudaFuncSetAttribute(attn_hmma,
                         cudaFuncAttributeMaxDynamicSharedMemorySize, ATT_SMEM);

    // 1) split-convert x; transpose+split weights
    convert_hl<<<(MM * CC) / (256 * 4), 256>>>(x, (__nv_bfloat16*)pxh, (__nv_bfloat16*)pxl);
    dim3 tcb(32, 8);
    transpose_convert<<<dim3(C3 / 32, CC / 32), tcb>>>(w_qkv,
        (__nv_bfloat16*)pwqh, (__nv_bfloat16*)pwql, CC, C3);
    transpose_convert<<<dim3(CC / 32, CC / 32), tcb>>>(w_proj,
        (__nv_bfloat16*)pwph, (__nv_bfloat16*)pwpl, CC, CC);

    // 2) QKV GEMM -> hi/lo bf16 qkv directly
    gemm_hmma<true><<<dim3(C3 / 128, MM / 128), 256, GEMM_SMEM>>>(
        (const __nv_bfloat16*)pxh, (const __nv_bfloat16*)pxl,
        (const __nv_bfloat16*)pwqh, (const __nv_bfloat16*)pwql,
        nullptr, (__nv_bfloat16*)pqh, (__nv_bfloat16*)pql, MM, C3, CC);

    // 3) HMMA flash attention (writes y hi/lo)
    attn_hmma<<<dim3(BB * HH, TT / 128), 256, ATT_SMEM>>>(
        (const __nv_bfloat16*)pqh, (const __nv_bfloat16*)pql,
        (__nv_bfloat16*)pyh, (__nv_bfloat16*)pyl);

    // 4) projection GEMM -> fp32 out
    gemm_hmma<false><<<dim3(CC / 128, MM / 128), 256, GEMM_SMEM>>>(
        (const __nv_bfloat16*)pyh, (const __nv_bfloat16*)pyl,
        (const __nv_bfloat16*)pwph, (const __nv_bfloat16*)pwpl,
        out, nullptr, nullptr, MM, CC, CC);
}

// round 15
// speedup vs baseline: 3.3108x; 1.1046x over previous
#include <cuda_runtime.h>
#include <cuda_bf16.h>
#include <math.h>
#include <stdint.h>

#define BB 2
#define TT 2048
#define CC 1024
#define HH 16
#define DD 64
#define C3 (3*CC)
#define MM (BB*TT)   // 4096

// ---------------- scratch (__device__ globals; allocation-free rule) -------
__device__ __nv_bfloat16 g_qkvh[(size_t)MM * C3];      // qkv hi [4096,3072]
__device__ __nv_bfloat16 g_qkvl[(size_t)MM * C3];      // qkv lo
__device__ __nv_bfloat16 g_xh[(size_t)MM * CC];
__device__ __nv_bfloat16 g_xl[(size_t)MM * CC];
__device__ __nv_bfloat16 g_wqkvT_h[(size_t)C3 * CC];   // w_qkv^T [3072,1024]
__device__ __nv_bfloat16 g_wqkvT_l[(size_t)C3 * CC];
__device__ __nv_bfloat16 g_wprojT_h[(size_t)CC * CC];  // w_proj^T [1024,1024]
__device__ __nv_bfloat16 g_wprojT_l[(size_t)CC * CC];
__device__ __nv_bfloat16 g_yh[(size_t)MM * CC];
__device__ __nv_bfloat16 g_yl[(size_t)MM * CC];

// ---------------- PTX helpers (baseline compute_103-legal) -----------------
__device__ __forceinline__ uint32_t smem_u32(const void* p) {
    uint32_t a;
    asm("{ .reg .u64 t; cvta.to.shared.u64 t, %1; cvt.u32.u64 %0, t; }"
        : "=r"(a) : "l"(p));
    return a;
}
__device__ __forceinline__ void cp16(uint32_t s, const void* g) {
    asm volatile("cp.async.cg.shared.global [%0], [%1], 16;"
                 :: "r"(s), "l"(g) : "memory");
}
__device__ __forceinline__ void cp_commit() {
    asm volatile("cp.async.commit_group;" ::: "memory");
}
template <int N>
__device__ __forceinline__ void cp_wait() {
    asm volatile("cp.async.wait_group %0;" :: "n"(N) : "memory");
}
__device__ __forceinline__ void ldm_x4(uint32_t* r, uint32_t a) {
    asm volatile("ldmatrix.sync.aligned.m8n8.x4.shared.b16 {%0,%1,%2,%3}, [%4];"
                 : "=r"(r[0]), "=r"(r[1]), "=r"(r[2]), "=r"(r[3]) : "r"(a));
}
__device__ __forceinline__ void ldm_x4_t(uint32_t* r, uint32_t a) {
    asm volatile("ldmatrix.sync.aligned.m8n8.x4.trans.shared.b16 {%0,%1,%2,%3}, [%4];"
                 : "=r"(r[0]), "=r"(r[1]), "=r"(r[2]), "=r"(r[3]) : "r"(a));
}
__device__ __forceinline__ void ldm_x2(uint32_t* r, uint32_t a) {
    asm volatile("ldmatrix.sync.aligned.m8n8.x2.shared.b16 {%0,%1}, [%2];"
                 : "=r"(r[0]), "=r"(r[1]) : "r"(a));
}
__device__ __forceinline__ void mma16816(float* c, const uint32_t* a, const uint32_t* b) {
    asm volatile(
        "mma.sync.aligned.m16n8k16.row.col.f32.bf16.bf16.f32 "
        "{%0,%1,%2,%3}, {%4,%5,%6,%7}, {%8,%9}, {%0,%1,%2,%3};"
        : "+f"(c[0]), "+f"(c[1]), "+f"(c[2]), "+f"(c[3])
        : "r"(a[0]), "r"(a[1]), "r"(a[2]), "r"(a[3]), "r"(b[0]), "r"(b[1]));
}
__device__ __forceinline__ void split_pack2(float a, float b, uint32_t& hi, uint32_t& lo) {
    __nv_bfloat16 ha = __float2bfloat16(a), hb = __float2bfloat16(b);
    __nv_bfloat16 la = __float2bfloat16(a - __bfloat162float(ha));
    __nv_bfloat16 lb = __float2bfloat16(b - __bfloat162float(hb));
    __nv_bfloat162 H(ha, hb), L(la, lb);
    hi = *(uint32_t*)&H; lo = *(uint32_t*)&L;
}

// ---------------------------------------------------------------------------
// Conversions
// ---------------------------------------------------------------------------
__global__ void convert_hl(const float* __restrict__ X,
                           __nv_bfloat16* __restrict__ H,
                           __nv_bfloat16* __restrict__ L) {
    int i = (blockIdx.x * blockDim.x + threadIdx.x) * 4;
    float4 v = *(const float4*)(X + i);
    float a[4] = {v.x, v.y, v.z, v.w};
    __nv_bfloat16 h[4], l[4];
#pragma unroll
    for (int j = 0; j < 4; j++) {
        h[j] = __float2bfloat16(a[j]);
        l[j] = __float2bfloat16(a[j] - __bfloat162float(h[j]));
    }
    *(__nv_bfloat162*)(H + i)     = __nv_bfloat162(h[0], h[1]);
    *(__nv_bfloat162*)(H + i + 2) = __nv_bfloat162(h[2], h[3]);
    *(__nv_bfloat162*)(L + i)     = __nv_bfloat162(l[0], l[1]);
    *(__nv_bfloat162*)(L + i + 2) = __nv_bfloat162(l[2], l[3]);
}

__global__ void transpose_convert(const float* __restrict__ W,
                                  __nv_bfloat16* __restrict__ Th,
                                  __nv_bfloat16* __restrict__ Tl,
                                  int K, int N) {
    __shared__ float t[32][33];
    int k0 = blockIdx.y * 32, n0 = blockIdx.x * 32;
    int tx = threadIdx.x, ty = threadIdx.y;
#pragma unroll
    for (int i = 0; i < 32; i += 8)
        t[ty + i][tx] = W[(size_t)(k0 + ty + i) * N + n0 + tx];
    __syncthreads();
#pragma unroll
    for (int i = 0; i < 32; i += 8) {
        float v = t[tx][ty + i];
        __nv_bfloat16 h = __float2bfloat16(v);
        __nv_bfloat16 l = __float2bfloat16(v - __bfloat162float(h));
        size_t o = (size_t)(n0 + ty + i) * K + k0 + tx;
        Th[o] = h; Tl[o] = l;
    }
}

// ---------------------------------------------------------------------------
// HMMA bf16x3 GEMM: 128x128 tile, 256 threads, BK=32, 3-stage cp.async
// pipeline, XOR-swizzled 64B rows (conflict-free, no padding), ONE barrier
// per chunk. SMEM: 3 stages x 32KB = 96KB -> 2 CTAs/SM.
// ---------------------------------------------------------------------------
#define GBK 32
#define GTILE 8192                     // 128 rows x 64B
#define GOFF_AH 0
#define GOFF_AL (1 * GTILE)
#define GOFF_BH (2 * GTILE)
#define GOFF_BL (3 * GTILE)
#define GSTAGE (4 * GTILE)             // 32768
#define GEMM_SMEM (3 * GSTAGE)         // 98304

// swizzled byte offset of 16B chunk (row, chunk) in a 128x64B tile
__device__ __forceinline__ uint32_t gsw(uint32_t row, uint32_t chunk) {
    return row * 64u + ((chunk ^ (row >> 1)) & 3u) * 16u;
}

template <bool SPLIT>
__global__ __launch_bounds__(256) void gemm_hmma(
    const __nv_bfloat16* __restrict__ Ah, const __nv_bfloat16* __restrict__ Al,
    const __nv_bfloat16* __restrict__ Bh, const __nv_bfloat16* __restrict__ Bl,
    float* __restrict__ C, __nv_bfloat16* __restrict__ Ch,
    __nv_bfloat16* __restrict__ Cl, int M, int N, int K)
{
    extern __shared__ __align__(128) char smem[];
    const uint32_t sb = smem_u32(smem);
    const int tid  = threadIdx.x;
    const int wid  = tid >> 5;
    const int lane = tid & 31;
    const int wm   = wid & 1;
    const int wn   = wid >> 1;
    const int bm   = blockIdx.y * 128;
    const int bn   = blockIdx.x * 128;

    const __nv_bfloat16* ah = Ah + (size_t)bm * K;
    const __nv_bfloat16* al = Al + (size_t)bm * K;
    const __nv_bfloat16* bh = Bh + (size_t)bn * K;
    const __nv_bfloat16* bl = Bl + (size_t)bn * K;

    float acc[4][4][4];
#pragma unroll
    for (int i = 0; i < 4; i++)
#pragma unroll
        for (int j = 0; j < 4; j++)
#pragma unroll
            for (int k = 0; k < 4; k++) acc[i][j][k] = 0.f;

    // loader: 512 16B-chunks per tile, 256 threads -> 2 chunks each, 4 tiles
    const uint32_t lr0 = (uint32_t)(tid >> 2);       // 0..63
    const uint32_t lc  = (uint32_t)(tid & 3);
    const uint32_t sw0 = gsw(lr0, lc);
    const uint32_t sw1 = gsw(lr0 + 64, lc);

    auto load_stage = [&](int slot, int k0) {
        const uint32_t s = sb + slot * GSTAGE;
        const size_t go0 = (size_t)lr0 * K + k0 + lc * 8;
        const size_t go1 = (size_t)(lr0 + 64) * K + k0 + lc * 8;
        cp16(s + GOFF_AH + sw0, ah + go0);  cp16(s + GOFF_AH + sw1, ah + go1);
        cp16(s + GOFF_AL + sw0, al + go0);  cp16(s + GOFF_AL + sw1, al + go1);
        cp16(s + GOFF_BH + sw0, bh + go0);  cp16(s + GOFF_BH + sw1, bh + go1);
        cp16(s + GOFF_BL + sw0, bl + go0);  cp16(s + GOFF_BL + sw1, bl + go1);
    };

    // ldmatrix lane addressing (rows/chunks; swizzle applied at use)
    const int tb = lane & 15;
    const uint32_t b_row  = wn * 32 + (tb & 7);
    const uint32_t b_chnk = (uint32_t)(tb >> 3);
    const uint32_t a_row  = wm * 64 + (lane & 7) + ((lane >> 3) & 1) * 8;
    const uint32_t a_chnk = (uint32_t)(lane >> 4);

    load_stage(0, 0);
    cp_commit();
    load_stage(1, GBK);
    cp_commit();

    const int NCH = K / GBK;
    int slot = 0;
    for (int ch = 0; ch < NCH; ch++) {
        cp_wait<1>();
        __syncthreads();
        if (ch + 2 < NCH) {
            int nslot = slot + 2; if (nslot >= 3) nslot -= 3;   // (slot+2) % 3
            load_stage(nslot, (ch + 2) * GBK);
        }
        cp_commit();     // exactly one group per iteration (may be empty at tail)

        const uint32_t s = sb + slot * GSTAGE;
#pragma unroll
        for (int ks = 0; ks < 2; ks++) {
            uint32_t bfh[4][2], bfl[4][2];
#pragma unroll
            for (int ni = 0; ni < 4; ni++) {
                uint32_t bo = gsw(b_row + ni * 8, b_chnk + ks * 2);
                ldm_x2(bfh[ni], s + GOFF_BH + bo);
                ldm_x2(bfl[ni], s + GOFF_BL + bo);
            }
#pragma unroll
            for (int mi = 0; mi < 4; mi++) {
                uint32_t ao = gsw(a_row + mi * 16, a_chnk + ks * 2);
                uint32_t afh[4], afl[4];
                ldm_x4(afh, s + GOFF_AH + ao);
                ldm_x4(afl, s + GOFF_AL + ao);
#pragma unroll
                for (int ni = 0; ni < 4; ni++) {
                    mma16816(acc[mi][ni], afh, bfh[ni]);
                    mma16816(acc[mi][ni], afh, bfl[ni]);
                    mma16816(acc[mi][ni], afl, bfh[ni]);
                }
            }
        }
        slot = (slot == 2) ? 0 : slot + 1;
    }

    const int g = lane >> 2, q = lane & 3;
#pragma unroll
    for (int mi = 0; mi < 4; mi++) {
        const int row = bm + wm * 64 + mi * 16 + g;
#pragma unroll
        for (int ni = 0; ni < 4; ni++) {
            const int col = bn + wn * 32 + ni * 8 + q * 2;
            if (SPLIT) {
                uint32_t h0, l0, h1, l1;
                split_pack2(acc[mi][ni][0], acc[mi][ni][1], h0, l0);
                split_pack2(acc[mi][ni][2], acc[mi][ni][3], h1, l1);
                size_t o0 = (size_t)row * N + col;
                size_t o1 = (size_t)(row + 8) * N + col;
                *(uint32_t*)(Ch + o0) = h0; *(uint32_t*)(Cl + o0) = l0;
                *(uint32_t*)(Ch + o1) = h1; *(uint32_t*)(Cl + o1) = l1;
            } else {
                float* cp0 = C + (size_t)row * N + col;
                float* cp1 = C + (size_t)(row + 8) * N + col;
                *(float2*)cp0 = make_float2(acc[mi][ni][0], acc[mi][ni][1]);
                *(float2*)cp1 = make_float2(acc[mi][ni][2], acc[mi][ni][3]);
            }
        }
    }
}

// ---------------------------------------------------------------------------
// HMMA flash attention (causal; reference window term is dead code).
// ---------------------------------------------------------------------------
#define AROW 144
#define A_OQH 0
#define A_OQL (128 * AROW)
#define A_STG (2 * 128 * AROW)
#define A_TILE (64 * AROW)
#define A_STAGE_BYTES (4 * A_TILE)
#define ATT_SMEM (A_STG + 2 * A_STAGE_BYTES)

__global__ __launch_bounds__(256) void attn_hmma(
    const __nv_bfloat16* __restrict__ qh, const __nv_bfloat16* __restrict__ ql,
    __nv_bfloat16* __restrict__ yh, __nv_bfloat16* __restrict__ yl)
{
    extern __shared__ __align__(128) char smem[];
    const uint32_t sb = smem_u32(smem);
    const int tid = threadIdx.x, lane = tid & 31, w = tid >> 5;
    const int bh = blockIdx.x, b = bh >> 4, h = bh & 15;
    const int rt = gridDim.y - 1 - blockIdx.y;
    const int r0 = rt * 128;
    const int wq0 = r0 + w * 16;

    {
        const int qt = tid >> 7;
        const __nv_bfloat16* src = qt ? ql : qh;
        const uint32_t dst = sb + (qt ? A_OQL : A_OQH);
#pragma unroll
        for (int j = 0; j < 8; j++) {
            int idx = (tid & 127) + j * 128;
            int row = idx >> 3, col = idx & 7;
            cp16(dst + row * AROW + col * 16,
                 src + ((size_t)(b * TT + r0 + row)) * C3 + h * DD + col * 8);
        }
    }
    cp_commit();

    auto load_stage = [&](int buf, int k0) {
        const int t4 = tid >> 6;
        const __nv_bfloat16* src = (t4 & 1) ? ql : qh;
        const int voff = (t4 >> 1) ? 2 * CC : CC;
        const uint32_t dst = sb + A_STG + buf * A_STAGE_BYTES + t4 * A_TILE;
#pragma unroll
        for (int j = 0; j < 8; j++) {
            int idx = (tid & 63) + j * 64;
            int row = idx >> 3, col = idx & 7;
            cp16(dst + row * AROW + col * 16,
                 src + ((size_t)(b * TT + k0 + row)) * C3 + voff + h * DD + col * 8);
        }
    };

    load_stage(0, 0);
    cp_commit();
    cp_wait<1>();
    __syncthreads();

    uint32_t qfh[4][4], qfl[4][4];
    {
        const uint32_t q_row = w * 16 + (lane & 7) + ((lane >> 3) & 1) * 8;
#pragma unroll
        for (int ks = 0; ks < 4; ks++) {
            uint32_t qa = sb + A_OQH + q_row * AROW + (ks * 2 + (lane >> 4)) * 16;
            ldm_x4(qfh[ks], qa);
            ldm_x4(qfl[ks], qa + A_OQL);
        }
    }

    float o[8][4];
#pragma unroll
    for (int i = 0; i < 8; i++)
#pragma unroll
        for (int j = 0; j < 4; j++) o[i][j] = 0.f;
    float m0 = -1e30f, m1 = -1e30f, l0 = 0.f, l1 = 0.f;

    const uint32_t k_row  = (lane & 7) + (lane >> 4) * 8;
    const uint32_t k_half = (lane >> 3) & 1;
    const uint32_t v_key  = lane & 15;
    const int rg0 = wq0 + (lane >> 2), rg1 = rg0 + 8;
    const int qq2 = (lane & 3) * 2;

    const int NT = 2 * rt + 2;
    for (int ch = 0; ch < NT; ch++) {
        const int buf = ch & 1;
        if (ch + 1 < NT) {
            load_stage(buf ^ 1, (ch + 1) * 64);
            cp_commit();
            cp_wait<1>();
        } else {
            cp_wait<0>();
        }
        __syncthreads();

        const int k0 = ch * 64;
        if (k0 <= wq0) {
            const uint32_t stg = sb + A_STG + buf * A_STAGE_BYTES;

            float s[8][4];
#pragma unroll
            for (int i = 0; i < 8; i++)
#pragma unroll
                for (int j = 0; j < 4; j++) s[i][j] = 0.f;

#pragma unroll
            for (int ks = 0; ks < 4; ks++) {
#pragma unroll
                for (int np = 0; np < 4; np++) {
                    uint32_t ka = stg + (np * 16 + k_row) * AROW
                                + (ks * 2 + k_half) * 16;
                    uint32_t kh4[4], kl4[4];
                    ldm_x4(kh4, ka);
                    ldm_x4(kl4, ka + A_TILE);
                    mma16816(s[2*np],   qfh[ks], kh4);
                    mma16816(s[2*np],   qfh[ks], kl4);
                    mma16816(s[2*np],   qfl[ks], kh4);
                    mma16816(s[2*np+1], qfh[ks], kh4 + 2);
                    mma16816(s[2*np+1], qfh[ks], kl4 + 2);
                    mma16816(s[2*np+1], qfl[ks], kh4 + 2);
                }
            }

            const bool need_mask = (wq0 - k0) < 64;
#pragma unroll
            for (int ni = 0; ni < 8; ni++) {
                int col = k0 + ni * 8 + qq2;
                float v0 = s[ni][0] * 0.125f, v1 = s[ni][1] * 0.125f;
                float v2 = s[ni][2] * 0.125f, v3 = s[ni][3] * 0.125f;
                if (need_mask) {
                    if (col     > rg0) v0 = -1e30f;
                    if (col + 1 > rg0) v1 = -1e30f;
                    if (col     > rg1) v2 = -1e30f;
                    if (col + 1 > rg1) v3 = -1e30f;
                }
                s[ni][0] = v0; s[ni][1] = v1; s[ni][2] = v2; s[ni][3] = v3;
            }

            float mx0 = -1e30f, mx1 = -1e30f;
#pragma unroll
            for (int ni = 0; ni < 8; ni++) {
                mx0 = fmaxf(mx0, fmaxf(s[ni][0], s[ni][1]));
                mx1 = fmaxf(mx1, fmaxf(s[ni][2], s[ni][3]));
            }
            mx0 = fmaxf(mx0, __shfl_xor_sync(0xffffffffu, mx0, 1));
            mx0 = fmaxf(mx0, __shfl_xor_sync(0xffffffffu, mx0, 2));
            mx1 = fmaxf(mx1, __shfl_xor_sync(0xffffffffu, mx1, 1));
            mx1 = fmaxf(mx1, __shfl_xor_sync(0xffffffffu, mx1, 2));

            float nm0 = fmaxf(m0, mx0), nm1 = fmaxf(m1, mx1);
            float cr0 = __expf(m0 - nm0), cr1 = __expf(m1 - nm1);
            float ps0 = 0.f, ps1 = 0.f;
#pragma unroll
            for (int ni = 0; ni < 8; ni++) {
                s[ni][0] = __expf(s[ni][0] - nm0);
                s[ni][1] = __expf(s[ni][1] - nm0);
                s[ni][2] = __expf(s[ni][2] - nm1);
                s[ni][3] = __expf(s[ni][3] - nm1);
                ps0 += s[ni][0] + s[ni][1];
                ps1 += s[ni][2] + s[ni][3];
            }
            ps0 += __shfl_xor_sync(0xffffffffu, ps0, 1);
            ps0 += __shfl_xor_sync(0xffffffffu, ps0, 2);
            ps1 += __shfl_xor_sync(0xffffffffu, ps1, 1);
            ps1 += __shfl_xor_sync(0xffffffffu, ps1, 2);
            l0 = l0 * cr0 + ps0;  l1 = l1 * cr1 + ps1;
            m0 = nm0;  m1 = nm1;
#pragma unroll
            for (int nd = 0; nd < 8; nd++) {
                o[nd][0] *= cr0; o[nd][1] *= cr0;
                o[nd][2] *= cr1; o[nd][3] *= cr1;
            }

#pragma unroll
            for (int ks = 0; ks < 4; ks++) {
                uint32_t ah[4], al[4];
                split_pack2(s[2*ks][0],   s[2*ks][1],   ah[0], al[0]);
                split_pack2(s[2*ks][2],   s[2*ks][3],   ah[1], al[1]);
                split_pack2(s[2*ks+1][0], s[2*ks+1][1], ah[2], al[2]);
                split_pack2(s[2*ks+1][2], s[2*ks+1][3], ah[3], al[3]);
#pragma unroll
                for (int np = 0; np < 4; np++) {
                    uint32_t va = stg + 2 * A_TILE + (ks * 16 + v_key) * AROW
                                + (np * 2 + (lane >> 4)) * 16;
                    uint32_t vh4[4], vl4[4];
                    ldm_x4_t(vh4, va);
                    ldm_x4_t(vl4, va + A_TILE);
                    mma16816(o[2*np],   ah, vh4);
                    mma16816(o[2*np],   ah, vl4);
                    mma16816(o[2*np],   al, vh4);
                    mma16816(o[2*np+1], ah, vh4 + 2);
                    mma16816(o[2*np+1], ah, vl4 + 2);
                    mma16816(o[2*np+1], al, vh4 + 2);
                }
            }
        }
        __syncthreads();
    }

    const float i0 = 1.f / l0, i1 = 1.f / l1;
    const size_t ob = ((size_t)(b * TT + rg0)) * CC + h * DD + qq2;
#pragma unroll
    for (int nd = 0; nd < 8; nd++) {
        uint32_t h0, lo0, h1, lo1;
        split_pack2(o[nd][0] * i0, o[nd][1] * i0, h0, lo0);
        split_pack2(o[nd][2] * i1, o[nd][3] * i1, h1, lo1);
        *(uint32_t*)(yh + ob + nd * 8) = h0;
        *(uint32_t*)(yl + ob + nd * 8) = lo0;
        *(uint32_t*)(yh + ob + 8 * CC + nd * 8) = h1;
        *(uint32_t*)(yl + ob + 8 * CC + nd * 8) = lo1;
    }
}

// ---------------------------------------------------------------------------
extern "C" void kernel_launch(void* const* d_in, const int* in_sizes, int n_in,
                              void* d_out, int out_size)
{
    const float* x      = (const float*)d_in[0];
    const float* w_qkv  = (const float*)d_in[1];
    const float* w_proj = (const float*)d_in[2];
    float* out = (float*)d_out;

    void *pqh, *pql, *pxh, *pxl, *pwqh, *pwql, *pwph, *pwpl, *pyh, *pyl;
    cudaGetSymbolAddress(&pqh, g_qkvh); cudaGetSymbolAddress(&pql, g_qkvl);
    cudaGetSymbolAddress(&pxh, g_xh);   cudaGetSymbolAddress(&pxl, g_xl);
    cudaGetSymbolAddress(&pwqh, g_wqkvT_h); cudaGetSymbolAddress(&pwql, g_wqkvT_l);
    cudaGetSymbolAddress(&pwph, g_wprojT_h); cudaGetSymbolAddress(&pwpl, g_wprojT_l);
    cudaGetSymbolAddress(&pyh, g_yh);   cudaGetSymbolAddress(&pyl, g_yl);

    cudaFuncSetAttribute(gemm_hmma<true>,
                         cudaFuncAttributeMaxDynamicSharedMemorySize, GEMM_SMEM);
    cudaFuncSetAttribute(gemm_hmma<false>,
                         cudaFuncAttributeMaxDynamicSharedMemorySize, GEMM_SMEM);
    cudaFuncSetAttribute(attn_hmma,
                         cudaFuncAttributeMaxDynamicSharedMemorySize, ATT_SMEM);

    convert_hl<<<(MM * CC) / (256 * 4), 256>>>(x, (__nv_bfloat16*)pxh, (__nv_bfloat16*)pxl);
    dim3 tcb(32, 8);
    transpose_convert<<<dim3(C3 / 32, CC / 32), tcb>>>(w_qkv,
        (__nv_bfloat16*)pwqh, (__nv_bfloat16*)pwql, CC, C3);
    transpose_convert<<<dim3(CC / 32, CC / 32), tcb>>>(w_proj,
        (__nv_bfloat16*)pwph, (__nv_bfloat16*)pwpl, CC, CC);

    gemm_hmma<true><<<dim3(C3 / 128, MM / 128), 256, GEMM_SMEM>>>(
        (const __nv_bfloat16*)pxh, (const __nv_bfloat16*)pxl,
        (const __nv_bfloat16*)pwqh, (const __nv_bfloat16*)pwql,
        nullptr, (__nv_bfloat16*)pqh, (__nv_bfloat16*)pql, MM, C3, CC);

    attn_hmma<<<dim3(BB * HH, TT / 128), 256, ATT_SMEM>>>(
        (const __nv_bfloat16*)pqh, (const __nv_bfloat16*)pql,
        (__nv_bfloat16*)pyh, (__nv_bfloat16*)pyl);

    gemm_hmma<false><<<dim3(CC / 128, MM / 128), 256, GEMM_SMEM>>>(
        (const __nv_bfloat16*)pyh, (const __nv_bfloat16*)pyl,
        (const __nv_bfloat16*)pwph, (const __nv_bfloat16*)pwpl,
        out, nullptr, nullptr, MM, CC, CC);
}